// round 2
// baseline (speedup 1.0000x reference)
#include <cuda_runtime.h>
#include <math.h>

// Problem constants
#define Bn   64
#define Tn   2048
#define Dn   64
#define Ln   2047            // T-1
#define Gn   4
#define GDn  16
#define OUTD 64
#define BTD  (Bn*Tn*Dn)      // 8388608
#define BT   (Bn*Tn)         // 131072

// Scratch (static device globals; no allocation)
__device__ float g_f[Bn*Ln*OUTD];     // projected features (B, T-1, 64)
__device__ float g_sig[Bn*OUTD];      // SE gates (B, 64)

__constant__ float c_invk[13] = {0.f, 1.f, 0.5f, (1.f/3.f), 0.25f, 0.2f,
                                 (1.f/6.f), (1.f/7.f), 0.125f, (1.f/9.f),
                                 0.1f, (1.f/11.f), (1.f/12.f)};

// 8x8 matmul, fully unrolled, DST = SRC @ SRC (DST must differ from SRC)
#define MM8(DST, SRC)                                                        \
  { _Pragma("unroll") for (int i_ = 0; i_ < 8; i_++) {                       \
      float r_[8];                                                           \
      _Pragma("unroll") for (int j_ = 0; j_ < 8; j_++) r_[j_] = 0.f;         \
      _Pragma("unroll") for (int k_ = 0; k_ < 8; k_++) {                     \
        float tv_ = SRC[i_*8 + k_];                                          \
        _Pragma("unroll") for (int j_ = 0; j_ < 8; j_++)                     \
          r_[j_] = fmaf(tv_, SRC[k_*8 + j_], r_[j_]);                        \
      }                                                                      \
      _Pragma("unroll") for (int j_ = 0; j_ < 8; j_++) DST[i_*8+j_] = r_[j_];\
  } }

// ---------------------------------------------------------------------------
// Kernel 1: per (b,t,g) Lie projection + expm + LayerNorm, then fused
// projection (256 -> 64) per (b,t). One block = 64 timesteps x 4 groups.
// ---------------------------------------------------------------------------
__global__ __launch_bounds__(256, 1) void k_f(
    const float* __restrict__ x, const float* __restrict__ mask,
    const float* __restrict__ Wd, const float* __restrict__ gam,
    const float* __restrict__ bet, const float* __restrict__ pw,
    const float* __restrict__ pb)
{
  extern __shared__ float sm[];
  float* sS = sm;                 // 4096 floats: skew S (G, GD, 8, 8)
  float* sw = sm + 4096;          // 16384 floats: proj_w (256, 64)
  float* sf = sm + 4096 + 16384;  // 64 * 257 floats: LN'd features

  const int tid = threadIdx.x;
  const int b   = blockIdx.y;
  const int t0  = blockIdx.x * 64;

  // Build skew-symmetric S = tril(W,-1) - tril(W,-1)^T in shared
  for (int idx = tid; idx < 4096; idx += 256) {
    int j  = idx & 7;
    int i  = (idx >> 3) & 7;
    int gd = idx >> 6;
    float v = 0.f;
    if (i > j) v  = Wd[gd*64 + i*8 + j];
    if (j > i) v -= Wd[gd*64 + j*8 + i];
    sS[idx] = v;
  }
  // Cache proj_w in shared (64 KB)
  {
    const float4* pw4 = (const float4*)pw;
    float4* sw4 = (float4*)sw;
    for (int idx = tid; idx < 4096; idx += 256) sw4[idx] = pw4[idx];
  }
  __syncthreads();

  const int g  = tid >> 6;   // warp-uniform group -> S reads are broadcasts
  const int tl = tid & 63;
  const int t  = t0 + tl;
  const bool valid = (t < Ln);

  // ---- Mlie = sum_d dX_d * S[g,d]  (lower triangle only; skew) ----
  float A[64];
  #pragma unroll
  for (int i = 0; i < 64; i++) A[i] = 0.f;

  if (valid) {
    const float mk = mask[b*Tn + t + 1];
    const float* xb = x + ((size_t)b*Tn + t)*Dn + g*GDn;
    #pragma unroll 1
    for (int d = 0; d < 16; d++) {
      float dxd = (xb[Dn + d] - xb[d]) * mk;
      const float* Sg = sS + (g*16 + d)*64;
      #pragma unroll
      for (int i = 1; i < 8; i++)
        #pragma unroll
        for (int j = 0; j < i; j++)
          A[i*8+j] = fmaf(dxd, Sg[i*8+j], A[i*8+j]);
    }
  }
  // scale by 1/2^s (s=6) and fill skew upper triangle
  #pragma unroll
  for (int i = 1; i < 8; i++)
    #pragma unroll
    for (int j = 0; j < i; j++) {
      float v = A[i*8+j] * (1.f/64.f);
      A[i*8+j] = v;
      A[j*8+i] = -v;
    }

  // ---- expm: Taylor-12 + 6 squarings (matches reference) ----
  float term[64], outm[64];
  #pragma unroll
  for (int i = 0; i < 64; i++) {
    float e = ((i & 7) == (i >> 3)) ? 1.f : 0.f;
    term[i] = e; outm[i] = e;
  }
  #pragma unroll 1
  for (int k = 1; k <= 12; k++) {
    const float invk = c_invk[k];
    #pragma unroll
    for (int i = 0; i < 8; i++) {
      float r[8];
      #pragma unroll
      for (int j = 0; j < 8; j++) r[j] = 0.f;
      #pragma unroll
      for (int kk = 0; kk < 8; kk++) {
        float tv = term[i*8 + kk];
        #pragma unroll
        for (int j = 0; j < 8; j++) r[j] = fmaf(tv, A[kk*8 + j], r[j]);
      }
      #pragma unroll
      for (int j = 0; j < 8; j++) {
        float nt = r[j] * invk;
        term[i*8+j] = nt;
        outm[i*8+j] += nt;
      }
    }
  }
  #pragma unroll 1
  for (int it = 0; it < 3; it++) {   // 6 squarings, ping-pong buffers
    MM8(term, outm);
    MM8(outm, term);
  }

  // ---- LayerNorm over the 64 entries (per group) ----
  float mu = 0.f;
  #pragma unroll
  for (int i = 0; i < 64; i++) mu += outm[i];
  mu *= (1.f/64.f);
  float var = 0.f;
  #pragma unroll
  for (int i = 0; i < 64; i++) { float d = outm[i] - mu; var += d*d; }
  var *= (1.f/64.f);
  const float rs = rsqrtf(var + 1e-5f);
  #pragma unroll
  for (int i = 0; i < 64; i++) {
    float v = fmaf((outm[i] - mu) * rs, __ldg(&gam[i]), __ldg(&bet[i]));
    sf[tl*257 + g*64 + i] = v;
  }
  __syncthreads();

  // ---- Projection: f256 @ proj_w + proj_b, 4o x 4t register tile ----
  const int o0  = (tid & 15) * 4;
  const int tp0 = (tid >> 4) * 4;
  float acc[4][4];
  {
    float4 pbv = *(const float4*)(pb + o0);
    #pragma unroll
    for (int ti = 0; ti < 4; ti++) {
      acc[ti][0] = pbv.x; acc[ti][1] = pbv.y;
      acc[ti][2] = pbv.z; acc[ti][3] = pbv.w;
    }
  }
  #pragma unroll 1
  for (int c = 0; c < 256; c++) {
    float4 wv = *(const float4*)(sw + c*64 + o0);
    #pragma unroll
    for (int ti = 0; ti < 4; ti++) {
      float fv = sf[(tp0 + ti)*257 + c];
      acc[ti][0] = fmaf(fv, wv.x, acc[ti][0]);
      acc[ti][1] = fmaf(fv, wv.y, acc[ti][1]);
      acc[ti][2] = fmaf(fv, wv.z, acc[ti][2]);
      acc[ti][3] = fmaf(fv, wv.w, acc[ti][3]);
    }
  }
  #pragma unroll
  for (int ti = 0; ti < 4; ti++) {
    int tt = t0 + tp0 + ti;
    if (tt < Ln) {
      float4 v = make_float4(acc[ti][0], acc[ti][1], acc[ti][2], acc[ti][3]);
      *(float4*)(g_f + ((size_t)b*Ln + tt)*64 + o0) = v;
    }
  }
}

// ---------------------------------------------------------------------------
// Kernel 2: h1 = x + lin_interp(f, T)  -> write into d_out
// ---------------------------------------------------------------------------
__global__ void k_interp(const float* __restrict__ x, float* __restrict__ out)
{
  int idx = blockIdx.x * blockDim.x + threadIdx.x;
  if (idx >= BTD) return;
  int b   = idx >> 17;          // T*D = 131072
  int r   = idx & 131071;
  int i   = r >> 6;
  int dch = r & 63;
  float pos = ((float)i + 0.5f) * (2047.0f/2048.0f) - 0.5f;
  pos = fminf(fmaxf(pos, 0.f), 2046.f);
  int i0 = (int)floorf(pos);
  int i1 = min(i0 + 1, 2046);
  float w = pos - (float)i0;
  const float* fb = g_f + (size_t)b*Ln*64;
  float f0 = fb[i0*64 + dch], f1 = fb[i1*64 + dch];
  out[idx] = x[idx] + f0*(1.f - w) + f1*w;
}

// ---------------------------------------------------------------------------
// Kernel 3: masked average pool over T, then SE MLP -> sigmoid gates.
// Deterministic fixed-order reductions (no float atomics).
// ---------------------------------------------------------------------------
__global__ void k_se(const float* __restrict__ h, const float* __restrict__ mask,
                     const float* __restrict__ w1, const float* __restrict__ b1,
                     const float* __restrict__ w2, const float* __restrict__ b2)
{
  __shared__ float sp[256], sd[256], spool[64], shid[4];
  const int b = blockIdx.x, tid = threadIdx.x;
  const int dch = tid & 63, sl = tid >> 6;
  const float* hb = h + (size_t)b*Tn*Dn;
  const float* mb = mask + b*Tn;

  float sum = 0.f;
  for (int t = sl; t < Tn; t += 4) sum = fmaf(hb[t*64 + dch], mb[t], sum);
  float den = 0.f;
  for (int t = tid; t < Tn; t += 256) den += mb[t];
  sp[tid] = sum; sd[tid] = den;
  __syncthreads();
  for (int s = 128; s > 0; s >>= 1) {
    if (tid < s) sd[tid] += sd[tid + s];
    __syncthreads();
  }
  if (tid < 64)
    spool[tid] = (sp[tid] + sp[tid+64] + sp[tid+128] + sp[tid+192]) / sd[0];
  __syncthreads();
  if (tid < 4) {
    float hh = b1[tid];
    for (int d = 0; d < 64; d++) hh = fmaf(spool[d], w1[d*4 + tid], hh);
    shid[tid] = 0.5f * hh * (1.f + erff(hh * 0.70710678118654752f)); // exact gelu
  }
  __syncthreads();
  if (tid < 64) {
    float o = b2[tid];
    #pragma unroll
    for (int j = 0; j < 4; j++) o = fmaf(shid[j], w2[j*64 + tid], o);
    g_sig[b*64 + tid] = 1.f / (1.f + expf(-o));
  }
}

// ---------------------------------------------------------------------------
// Kernel 4: out = h1 * s + x  (h1 already in d_out), plus mask tail copy.
// ---------------------------------------------------------------------------
__global__ void k_final(const float* __restrict__ x, const float* __restrict__ mask,
                        float* __restrict__ out, int n)
{
  int idx = blockIdx.x * blockDim.x + threadIdx.x;
  if (idx < BTD) {
    int b = idx >> 17;
    int dch = idx & 63;
    out[idx] = fmaf(out[idx], g_sig[b*64 + dch], x[idx]);
  } else if (idx < n) {
    int r = idx - BTD;
    out[idx] = (r < BT) ? mask[r] : 0.f;
  }
}

// ---------------------------------------------------------------------------
extern "C" void kernel_launch(void* const* d_in, const int* in_sizes, int n_in,
                              void* d_out, int out_size)
{
  const float* x    = (const float*)d_in[0];
  const float* mask = (const float*)d_in[1];
  const float* Wd   = (const float*)d_in[2];
  const float* gam  = (const float*)d_in[3];
  const float* bet  = (const float*)d_in[4];
  const float* pw   = (const float*)d_in[5];
  const float* pb   = (const float*)d_in[6];
  const float* w1   = (const float*)d_in[7];
  const float* b1   = (const float*)d_in[8];
  const float* w2   = (const float*)d_in[9];
  const float* b2   = (const float*)d_in[10];
  float* out = (float*)d_out;

  const int smem = (4096 + 16384 + 64*257) * 4;   // 147712 B
  cudaFuncSetAttribute(k_f, cudaFuncAttributeMaxDynamicSharedMemorySize, smem);

  dim3 g1(32, Bn);   // 32 t-chunks x 64 batches
  k_f<<<g1, 256, smem>>>(x, mask, Wd, gam, bet, pw, pb);
  k_interp<<<(BTD + 255)/256, 256>>>(x, out);
  k_se<<<Bn, 256>>>(out, mask, w1, b1, w2, b2);
  k_final<<<(out_size + 255)/256, 256>>>(x, mask, out, out_size);
}

// round 3
// speedup vs baseline: 1.1244x; 1.1244x over previous
#include <cuda_runtime.h>
#include <math.h>

// Problem constants
#define Bn   64
#define Tn   2048
#define Dn   64
#define Ln   2047            // T-1
#define Gn   4
#define GDn  16
#define OUTD 64
#define BTD  (Bn*Tn*Dn)      // 8388608
#define BT   (Bn*Tn)         // 131072

// Scratch (static device globals; no allocation)
__device__ float g_f[Bn*Ln*OUTD];     // projected features (B, T-1, 64)
__device__ float g_sig[Bn*OUTD];      // SE gates (B, 64)

// ---------------- packed f32x2 helpers ----------------
__device__ __forceinline__ unsigned long long ffma2(unsigned long long a,
                                                    unsigned long long b,
                                                    unsigned long long c) {
  unsigned long long d;
  asm("fma.rn.f32x2 %0, %1, %2, %3;" : "=l"(d) : "l"(a), "l"(b), "l"(c));
  return d;
}
__device__ __forceinline__ unsigned long long pk2(float lo, float hi) {
  unsigned long long d;
  asm("mov.b64 %0, {%1, %2};" : "=l"(d) : "f"(lo), "f"(hi));
  return d;
}
__device__ __forceinline__ float2 upk2(unsigned long long v) {
  float2 r;
  asm("mov.b64 {%0, %1}, %2;" : "=f"(r.x), "=f"(r.y) : "l"(v));
  return r;
}

// ---------------- triangular access (compile-time folded after unroll) ----
__device__ __forceinline__ float getA(const float* a, int i, int j) {
  // skew-symmetric, lower triangle stored (i>j), zero diagonal
  if (i == j) return 0.f;
  return (i > j) ? a[i*(i-1)/2 + j] : -a[j*(j-1)/2 + i];
}
__device__ __forceinline__ float getS6(const float* m, int i, int j) {
  // symmetric, lower triangle + diag stored
  return (i >= j) ? m[i*(i+1)/2 + j] : m[j*(j+1)/2 + i];
}

// full 8x8 matmul DST = SRC @ SRC (DST != SRC), scalar FFMA
#define MM8(DST, SRC)                                                        \
  { _Pragma("unroll") for (int i_ = 0; i_ < 8; i_++) {                       \
      float r_[8];                                                           \
      _Pragma("unroll") for (int j_ = 0; j_ < 8; j_++) r_[j_] = 0.f;         \
      _Pragma("unroll") for (int k_ = 0; k_ < 8; k_++) {                     \
        float tv_ = SRC[i_*8 + k_];                                          \
        _Pragma("unroll") for (int j_ = 0; j_ < 8; j_++)                     \
          r_[j_] = fmaf(tv_, SRC[k_*8 + j_], r_[j_]);                        \
      }                                                                      \
      _Pragma("unroll") for (int j_ = 0; j_ < 8; j_++) DST[i_*8+j_] = r_[j_];\
  } }

// ---------------------------------------------------------------------------
// Kernel 1: per (b,t,g) Lie projection + expm (PS Taylor-9, s=3, sym/skew
// structure) + LayerNorm, then fused projection (256 -> 64) per (b,t).
// One block = 64 timesteps x 4 groups.
// ---------------------------------------------------------------------------
__global__ __launch_bounds__(256, 1) void k_f(
    const float* __restrict__ x, const float* __restrict__ mask,
    const float* __restrict__ Wd, const float* __restrict__ gam,
    const float* __restrict__ bet, const float* __restrict__ pw,
    const float* __restrict__ pb)
{
  extern __shared__ float sm[];
  float* sS  = sm;                   // 4096 floats: skew S (G, GD, 8, 8)
  float* sw  = sm + 4096;            // 16384 floats: proj_w (256, 64)
  float* sf2 = sm + 4096 + 16384;    // 256 x 68: LN'd features, [c][t] layout

  const int tid = threadIdx.x;
  const int b   = blockIdx.y;
  const int t0  = blockIdx.x * 64;

  // Build skew-symmetric S = tril(W,-1) - tril(W,-1)^T in shared
  for (int idx = tid; idx < 4096; idx += 256) {
    int j  = idx & 7;
    int i  = (idx >> 3) & 7;
    int gd = idx >> 6;
    float v = 0.f;
    if (i > j) v  = Wd[gd*64 + i*8 + j];
    if (j > i) v -= Wd[gd*64 + j*8 + i];
    sS[idx] = v;
  }
  // Cache proj_w in shared (64 KB)
  {
    const float4* pw4 = (const float4*)pw;
    float4* sw4 = (float4*)sw;
    for (int idx = tid; idx < 4096; idx += 256) sw4[idx] = pw4[idx];
  }
  __syncthreads();

  const int g  = tid >> 6;   // warp-uniform group -> S reads are broadcasts
  const int tl = tid & 63;
  const int t  = t0 + tl;
  const bool valid = (t < Ln);

  // ---- A = (1/8) * sum_d dX_d * S[g,d]   (skew; lower triangle a[28]) ----
  float a[28];
  #pragma unroll
  for (int i = 0; i < 28; i++) a[i] = 0.f;

  if (valid) {
    const float mk = mask[b*Tn + t + 1];
    const float* xb = x + ((size_t)b*Tn + t)*Dn + g*GDn;
    #pragma unroll 1
    for (int d = 0; d < 16; d++) {
      float dxd = (xb[Dn + d] - xb[d]) * mk;
      const float* Sg = sS + (g*16 + d)*64;
      #pragma unroll
      for (int i = 1; i < 8; i++)
        #pragma unroll
        for (int j = 0; j < i; j++)
          a[i*(i-1)/2 + j] = fmaf(dxd, Sg[i*8+j], a[i*(i-1)/2 + j]);
    }
  }
  #pragma unroll
  for (int i = 0; i < 28; i++) a[i] *= 0.125f;   // scale 1/2^s, s=3

  // ---- B = A^2 (symmetric, 36 entries) ----
  float Bm[36];
  #pragma unroll
  for (int i = 0; i < 8; i++)
    #pragma unroll
    for (int j = 0; j <= i; j++) {
      float s = 0.f;
      #pragma unroll
      for (int k = 0; k < 8; k++) s = fmaf(getA(a,i,k), getA(a,k,j), s);
      Bm[i*(i+1)/2 + j] = s;
    }

  // ---- C = B^2 (symmetric) ----
  float Cm[36];
  #pragma unroll
  for (int i = 0; i < 8; i++)
    #pragma unroll
    for (int j = 0; j <= i; j++) {
      float s = 0.f;
      #pragma unroll
      for (int k = 0; k < 8; k++) s = fmaf(getS6(Bm,i,k), getS6(Bm,k,j), s);
      Cm[i*(i+1)/2 + j] = s;
    }

  // ---- V = I + B/2 + C*(I/24 + B/720 + C/40320)  (even part, symmetric) ----
  float Tm[36], Vm[36];
  #pragma unroll
  for (int i = 0; i < 8; i++)
    #pragma unroll
    for (int j = 0; j <= i; j++) {
      int q = i*(i+1)/2 + j;
      float e = (i == j) ? 1.f : 0.f;
      Tm[q] = e*(1.f/24.f) + Bm[q]*(1.f/720.f) + Cm[q]*(1.f/40320.f);
    }
  #pragma unroll
  for (int i = 0; i < 8; i++)
    #pragma unroll
    for (int j = 0; j <= i; j++) {
      float s = ((i == j) ? 1.f : 0.f) + 0.5f*getS6(Bm,i,j);
      #pragma unroll
      for (int k = 0; k < 8; k++) s = fmaf(getS6(Cm,i,k), getS6(Tm,k,j), s);
      Vm[i*(i+1)/2 + j] = s;
    }

  // ---- P = I + B/6 + C*(I/120 + B/5040 + C/362880) (odd inner, symmetric) --
  float Pm[36];
  #pragma unroll
  for (int i = 0; i < 8; i++)
    #pragma unroll
    for (int j = 0; j <= i; j++) {
      int q = i*(i+1)/2 + j;
      float e = (i == j) ? 1.f : 0.f;
      Tm[q] = e*(1.f/120.f) + Bm[q]*(1.f/5040.f) + Cm[q]*(1.f/362880.f);
    }
  #pragma unroll
  for (int i = 0; i < 8; i++)
    #pragma unroll
    for (int j = 0; j <= i; j++) {
      float s = ((i == j) ? 1.f : 0.f) + (1.f/6.f)*getS6(Bm,i,j);
      #pragma unroll
      for (int k = 0; k < 8; k++) s = fmaf(getS6(Cm,i,k), getS6(Tm,k,j), s);
      Pm[i*(i+1)/2 + j] = s;
    }

  // ---- U = A * P (skew since P commutes with A; lower triangle) ----
  float u[28];
  #pragma unroll
  for (int i = 1; i < 8; i++)
    #pragma unroll
    for (int j = 0; j < i; j++) {
      float s = 0.f;
      #pragma unroll
      for (int k = 0; k < 8; k++) s = fmaf(getA(a,i,k), getS6(Pm,k,j), s);
      u[i*(i-1)/2 + j] = s;
    }

  // ---- M = V + U ; three squarings (s=3) ----
  float m0[64], m1[64];
  #pragma unroll
  for (int i = 0; i < 8; i++)
    #pragma unroll
    for (int j = 0; j < 8; j++)
      m0[i*8+j] = getS6(Vm,i,j) + getA(u,i,j);
  MM8(m1, m0);
  MM8(m0, m1);
  MM8(m1, m0);

  // ---- LayerNorm over the 64 entries (per group); store transposed ----
  float mu = 0.f;
  #pragma unroll
  for (int i = 0; i < 64; i++) mu += m1[i];
  mu *= (1.f/64.f);
  float var = 0.f;
  #pragma unroll
  for (int i = 0; i < 64; i++) { float d = m1[i] - mu; var += d*d; }
  var *= (1.f/64.f);
  const float rs = rsqrtf(var + 1e-5f);
  #pragma unroll
  for (int i = 0; i < 64; i++) {
    float v = fmaf((m1[i] - mu) * rs, __ldg(&gam[i]), __ldg(&bet[i]));
    sf2[(g*64 + i)*68 + tl] = v;     // [c][t] layout, conflict-free
  }
  __syncthreads();

  // ---- Projection: f256 @ proj_w + proj_b, packed f32x2, 4t x 4o tile ----
  const int o0  = (tid & 15) * 4;
  const int tp0 = (tid >> 4) * 4;
  unsigned long long acc[4][2];
  {
    float4 pbv = *(const float4*)(pb + o0);
    unsigned long long p01 = pk2(pbv.x, pbv.y), p23 = pk2(pbv.z, pbv.w);
    #pragma unroll
    for (int ti = 0; ti < 4; ti++) { acc[ti][0] = p01; acc[ti][1] = p23; }
  }
  #pragma unroll 2
  for (int c = 0; c < 256; c++) {
    float4 fv = *(const float4*)(sf2 + c*68 + tp0);
    ulonglong2 wv = *(const ulonglong2*)(sw + c*64 + o0);
    unsigned long long f0 = pk2(fv.x, fv.x);
    unsigned long long f1 = pk2(fv.y, fv.y);
    unsigned long long f2 = pk2(fv.z, fv.z);
    unsigned long long f3 = pk2(fv.w, fv.w);
    acc[0][0] = ffma2(f0, wv.x, acc[0][0]); acc[0][1] = ffma2(f0, wv.y, acc[0][1]);
    acc[1][0] = ffma2(f1, wv.x, acc[1][0]); acc[1][1] = ffma2(f1, wv.y, acc[1][1]);
    acc[2][0] = ffma2(f2, wv.x, acc[2][0]); acc[2][1] = ffma2(f2, wv.y, acc[2][1]);
    acc[3][0] = ffma2(f3, wv.x, acc[3][0]); acc[3][1] = ffma2(f3, wv.y, acc[3][1]);
  }
  #pragma unroll
  for (int ti = 0; ti < 4; ti++) {
    int tt = t0 + tp0 + ti;
    if (tt < Ln) {
      float2 lo = upk2(acc[ti][0]), hi = upk2(acc[ti][1]);
      float4 v = make_float4(lo.x, lo.y, hi.x, hi.y);
      *(float4*)(g_f + ((size_t)b*Ln + tt)*64 + o0) = v;
    }
  }
}

// ---------------------------------------------------------------------------
// interp helper: position/weights for output index i (0..2047)
// ---------------------------------------------------------------------------
__device__ __forceinline__ void interp_idx(int i, int& i0, int& i1, float& w) {
  float pos = ((float)i + 0.5f) * (2047.0f/2048.0f) - 0.5f;
  pos = fminf(fmaxf(pos, 0.f), 2046.f);
  i0 = (int)floorf(pos);
  i1 = min(i0 + 1, 2046);
  w  = pos - (float)i0;
}

// ---------------------------------------------------------------------------
// Kernel 2: masked average pool over T of h = x + interp(f), SE MLP -> gates.
// Deterministic fixed-order reductions (no float atomics).
// ---------------------------------------------------------------------------
__global__ void k_se(const float* __restrict__ x, const float* __restrict__ mask,
                     const float* __restrict__ w1, const float* __restrict__ b1,
                     const float* __restrict__ w2, const float* __restrict__ b2)
{
  __shared__ float sp[256], sd[256], spool[64], shid[4];
  const int b = blockIdx.x, tid = threadIdx.x;
  const int dch = tid & 63, sl = tid >> 6;
  const float* xb = x + (size_t)b*Tn*Dn;
  const float* fb = g_f + (size_t)b*Ln*64;
  const float* mb = mask + b*Tn;

  float sum = 0.f;
  for (int t = sl; t < Tn; t += 4) {
    int i0, i1; float w;
    interp_idx(t, i0, i1, w);
    float fi = fb[i0*64 + dch]*(1.f - w) + fb[i1*64 + dch]*w;
    sum = fmaf(xb[t*64 + dch] + fi, mb[t], sum);
  }
  float den = 0.f;
  for (int t = tid; t < Tn; t += 256) den += mb[t];
  sp[tid] = sum; sd[tid] = den;
  __syncthreads();
  for (int s = 128; s > 0; s >>= 1) {
    if (tid < s) sd[tid] += sd[tid + s];
    __syncthreads();
  }
  if (tid < 64)
    spool[tid] = (sp[tid] + sp[tid+64] + sp[tid+128] + sp[tid+192]) / sd[0];
  __syncthreads();
  if (tid < 4) {
    float hh = b1[tid];
    for (int d = 0; d < 64; d++) hh = fmaf(spool[d], w1[d*4 + tid], hh);
    shid[tid] = 0.5f * hh * (1.f + erff(hh * 0.70710678118654752f)); // exact gelu
  }
  __syncthreads();
  if (tid < 64) {
    float o = b2[tid];
    #pragma unroll
    for (int j = 0; j < 4; j++) o = fmaf(shid[j], w2[j*64 + tid], o);
    g_sig[b*64 + tid] = 1.f / (1.f + expf(-o));
  }
}

// ---------------------------------------------------------------------------
// Kernel 3: out = (x + interp(f)) * sig + x, plus mask tail copy.
// ---------------------------------------------------------------------------
__global__ void k_final(const float* __restrict__ x, const float* __restrict__ mask,
                        float* __restrict__ out, int n)
{
  int idx = blockIdx.x * blockDim.x + threadIdx.x;
  if (idx < BTD) {
    int b   = idx >> 17;          // T*D = 131072
    int r   = idx & 131071;
    int ti  = r >> 6;
    int dch = r & 63;
    int i0, i1; float w;
    interp_idx(ti, i0, i1, w);
    const float* fb = g_f + (size_t)b*Ln*64;
    float fi = fb[i0*64 + dch]*(1.f - w) + fb[i1*64 + dch]*w;
    float xv = x[idx];
    out[idx] = fmaf(xv + fi, g_sig[b*64 + dch], xv);
  } else if (idx < n) {
    int r = idx - BTD;
    out[idx] = (r < BT) ? mask[r] : 0.f;
  }
}

// ---------------------------------------------------------------------------
extern "C" void kernel_launch(void* const* d_in, const int* in_sizes, int n_in,
                              void* d_out, int out_size)
{
  const float* x    = (const float*)d_in[0];
  const float* mask = (const float*)d_in[1];
  const float* Wd   = (const float*)d_in[2];
  const float* gam  = (const float*)d_in[3];
  const float* bet  = (const float*)d_in[4];
  const float* pw   = (const float*)d_in[5];
  const float* pb   = (const float*)d_in[6];
  const float* w1   = (const float*)d_in[7];
  const float* b1   = (const float*)d_in[8];
  const float* w2   = (const float*)d_in[9];
  const float* b2   = (const float*)d_in[10];
  float* out = (float*)d_out;

  const int smem = (4096 + 16384 + 256*68) * 4;   // 151552 B
  cudaFuncSetAttribute(k_f, cudaFuncAttributeMaxDynamicSharedMemorySize, smem);

  dim3 g1(32, Bn);   // 32 t-chunks x 64 batches
  k_f<<<g1, 256, smem>>>(x, mask, Wd, gam, bet, pw, pb);
  k_se<<<Bn, 256>>>(x, mask, w1, b1, w2, b2);
  k_final<<<(out_size + 255)/256, 256>>>(x, mask, out, out_size);
}